// round 6
// baseline (speedup 1.0000x reference)
#include <cuda_runtime.h>
#include <math.h>

#define MEM_SIZE 512

// ---- L2 persistence via cache-policy operand (sm_103-legal encoding) ----
__device__ __forceinline__ unsigned long long mk_policy() {
    unsigned long long pol;
    asm volatile("createpolicy.fractional.L2::evict_last.b64 %0, 1.0;" : "=l"(pol));
    return pol;
}
__device__ __forceinline__ float4 ldg_el4(const float4* p, unsigned long long pol) {
    float4 v;
    asm volatile("ld.global.nc.L2::cache_hint.v4.f32 {%0,%1,%2,%3}, [%4], %5;"
                 : "=f"(v.x), "=f"(v.y), "=f"(v.z), "=f"(v.w) : "l"(p), "l"(pol));
    return v;
}
__device__ __forceinline__ int ldg_eli(const int* p, unsigned long long pol) {
    int v;
    asm volatile("ld.global.nc.L2::cache_hint.s32 %0, [%1], %2;" : "=r"(v) : "l"(p), "l"(pol));
    return v;
}
__device__ __forceinline__ float ldg_elf(const float* p, unsigned long long pol) {
    float v;
    asm volatile("ld.global.nc.L2::cache_hint.f32 %0, [%1], %2;" : "=f"(v) : "l"(p), "l"(pol));
    return v;
}

// ---- faithful smooth-gate helpers (jax.nn.sigmoid branch structure) ----
__device__ __forceinline__ float sigm_(float z) {
    if (z >= 0.0f) {
        return 1.0f / (1.0f + expf(-z));
    } else {
        float e = expf(z);
        return e / (1.0f + e);
    }
}
__device__ __forceinline__ float silu_(float z) { return z * sigm_(z); }

// silu_threshold(x) = (silu(20x+10) - silu(20x-10)) / 20
__device__ __forceinline__ float thr_(float x) {
    float d = 20.0f * x;
    return (silu_(d + 10.0f) - silu_(d - 10.0f)) / 20.0f;
}

// fp32(exp(-20)): eq_gate value at |diff|=1 (negated at |diff|=2)
#define EGATE 2.0611536e-9f

// Reconstruct read_memory from 8 contiguous floats [b0, b0+8) and t = p - b0.
// result = m[p] + E * (m[p-1] + m[p+1] - m[p-2] - m[p+2]); out-of-range lanes
// are absent from the 8-lane window (b0 clamped to [0,504]).
__device__ __forceinline__ float combine_window(float4 f0, float4 f1, int t) {
    float4 fc;
    fc.x = (t < 4) ? f0.x : f1.x;
    fc.y = (t < 4) ? f0.y : f1.y;
    fc.z = (t < 4) ? f0.z : f1.z;
    fc.w = (t < 4) ? f0.w : f1.w;
    int tl = t & 3;
    float a0 = (tl & 1) ? fc.y : fc.x;
    float a1 = (tl & 1) ? fc.w : fc.z;
    float c  = (tl & 2) ? a1 : a0;

    float A = 0.0f;
#define LANE_ACC(vj, j) { int d = (j) - t; int ad = (d < 0) ? -d : d;            \
        A += (ad == 1) ? (vj) : ((ad == 2) ? -(vj) : 0.0f); }
    LANE_ACC(f0.x, 0) LANE_ACC(f0.y, 1) LANE_ACC(f0.z, 2) LANE_ACC(f0.w, 3)
    LANE_ACC(f1.x, 4) LANE_ACC(f1.y, 5) LANE_ACC(f1.z, 6) LANE_ACC(f1.w, 7)
#undef LANE_ACC
    return c + EGATE * A;
}

// Two threads per row: even lane gathers the pc-window (-> inst),
// odd lane gathers the sp-window (-> st); shfl merges, even lane finishes.
__global__ void __launch_bounds__(256)
c4moe_step_kernel(const int* __restrict__ pc,
                  const int* __restrict__ sp,
                  const int* __restrict__ bp,
                  const float* __restrict__ axp,
                  const float* __restrict__ memory,
                  float* __restrict__ out,
                  int B)
{
    int g = blockIdx.x * blockDim.x + threadIdx.x;
    int row = g >> 1;
    if (row >= B) return;            // never taken mid-warp (2*B % 256 == 0)
    bool isA = (g & 1) == 0;

    unsigned long long pol = mk_policy();
    const float* mem = memory + (size_t)row * MEM_SIZE;

    // ---- front-load every memory request (max MLP before any math) ----
    int p = isA ? ldg_eli(pc + row, pol) : ldg_eli(sp + row, pol);
    float ax = ldg_elf(axp + row, pol);
    int bpv = isA ? ldg_eli(bp + row, pol) : 0;

    int b0 = max(p - 2, 0) & ~3;  b0 = min(b0, MEM_SIZE - 8);
    float4 f0 = ldg_el4((const float4*)(mem + b0), pol);
    float4 f1 = ldg_el4((const float4*)(mem + b0 + 4), pol);

    float val = combine_window(f0, f1, p - b0);
    float other = __shfl_xor_sync(0xffffffffu, val, 1);

    if (!isA) return;                // odd lanes done

    float inst = val;
    float st   = other;

    // opcode = remainder(inst, 256) [numpy semantics: result in [0,256)]
    float opcode = fmodf(inst, 256.0f);
    if (opcode < 0.0f) opcode += 256.0f;
    float imm = floorf(inst / 256.0f);

    // argmax over eq_gate(opcode, 0..39): nearest integer; out-of-range -> score 0
    int sel = (int)rintf(opcode);
    if (sel < 0)  sel = 0;
    if (sel > 39) sel = 39;
    float ds = opcode - (float)sel;
    float score = thr_(ds + 0.5f) * thr_(0.5f - ds);

    // ax_safe = ax + eq_gate(ax,0)*0.001 (only ax==0 survives fp32 rounding)
    float ax_safe = (ax == 0.0f) ? 0.001f : ax;

    float out_v;
    switch (sel) {
        case 0: out_v = imm; break;
        case 1: out_v = (float)bpv + imm; break;
        case 2: out_v = st + ax; break;
        case 3: out_v = st - ax; break;
        case 4: out_v = st * ax; break;  // swiglu_mul(a,b) == a*b
        case 5:
        case 6: {
            // div_expert: q <= floor((st+0.5)/a), zero outside [0,63]
            float fq = floorf((st + 0.5f) / ax_safe);
            float divr = (fq >= 0.0f && fq < 64.0f) ? fq : 0.0f;
            out_v = (sel == 5) ? divr : (st - divr * ax_safe);
            break;
        }
        case 7: out_v = st * exp2f(ax); break;            // shl
        case 8: out_v = floorf(st / exp2f(ax)); break;    // shr
        case 9:
        case 10:
        case 11: {
            // extract_bits over k<16 == 16-bit integer bitwise ops on floor(st)
            int sf = ((int)floorf(st)) & 0xFFFF;
            int af = ((int)floorf(ax)) & 0xFFFF;
            int r = (sel == 9) ? (sf & af) : (sel == 10) ? (sf | af) : (sf ^ af);
            out_v = (float)r;
            break;
        }
        case 12:
        case 13: {
            float d = st - ax;
            float eqo = thr_(d + 0.5f) * thr_(0.5f - d);
            out_v = (sel == 12) ? eqo : (1.0f - eqo);
            break;
        }
        case 14: out_v = thr_(ax - st - 0.5f); break;  // gt_gate(ax, st)
        case 15: out_v = thr_(st - ax - 0.5f); break;  // gt_gate(st, ax)
        case 16: out_v = thr_(ax - st + 0.5f); break;  // ge_gate(ax, st)
        case 17: out_v = thr_(st - ax + 0.5f); break;  // ge_gate(st, ax)
        default: out_v = ax; break;                     // noop experts 18..39
    }

    out[row] = out_v * score;
}

extern "C" void kernel_launch(void* const* d_in, const int* in_sizes, int n_in,
                              void* d_out, int out_size) {
    const int*   pc  = (const int*)d_in[0];
    const int*   sp  = (const int*)d_in[1];
    const int*   bp  = (const int*)d_in[2];
    const float* ax  = (const float*)d_in[3];
    const float* mem = (const float*)d_in[4];
    float* out = (float*)d_out;
    int B = in_sizes[0];
    int threads = 256;
    long long total = 2LL * B;
    int blocks = (int)((total + threads - 1) / threads);
    c4moe_step_kernel<<<blocks, threads>>>(pc, sp, bp, ax, mem, out, B);
}

// round 7
// speedup vs baseline: 1.5724x; 1.5724x over previous
#include <cuda_runtime.h>
#include <math.h>

#define MEM_SIZE 512

// ---- faithful smooth-gate helpers (jax.nn.sigmoid branch structure) ----
__device__ __forceinline__ float sigm_(float z) {
    if (z >= 0.0f) {
        return 1.0f / (1.0f + expf(-z));
    } else {
        float e = expf(z);
        return e / (1.0f + e);
    }
}
__device__ __forceinline__ float silu_(float z) { return z * sigm_(z); }

// silu_threshold(x) = (silu(20x+10) - silu(20x-10)) / 20
__device__ __forceinline__ float thr_(float x) {
    float d = 20.0f * x;
    return (silu_(d + 10.0f) - silu_(d - 10.0f)) / 20.0f;
}

// fp32(exp(-20)): eq_gate value at |diff|=1 (negated at |diff|=2)
#define EGATE 2.0611536e-9f

// Reconstruct read_memory from 8 contiguous floats [b0, b0+8) and t = p - b0.
// result = m[p] + E * (m[p-1] + m[p+1] - m[p-2] - m[p+2]); out-of-range lanes
// are absent from the 8-lane window (b0 clamped to [0,504]).
__device__ __forceinline__ float combine_window(float4 f0, float4 f1, int t) {
    float4 fc;
    fc.x = (t < 4) ? f0.x : f1.x;
    fc.y = (t < 4) ? f0.y : f1.y;
    fc.z = (t < 4) ? f0.z : f1.z;
    fc.w = (t < 4) ? f0.w : f1.w;
    int tl = t & 3;
    float a0 = (tl & 1) ? fc.y : fc.x;
    float a1 = (tl & 1) ? fc.w : fc.z;
    float c  = (tl & 2) ? a1 : a0;

    float A = 0.0f;
#define LANE_ACC(vj, j) { int d = (j) - t; int ad = (d < 0) ? -d : d;            \
        A += (ad == 1) ? (vj) : ((ad == 2) ? -(vj) : 0.0f); }
    LANE_ACC(f0.x, 0) LANE_ACC(f0.y, 1) LANE_ACC(f0.z, 2) LANE_ACC(f0.w, 3)
    LANE_ACC(f1.x, 4) LANE_ACC(f1.y, 5) LANE_ACC(f1.z, 6) LANE_ACC(f1.w, 7)
#undef LANE_ACC
    return c + EGATE * A;
}

// Two threads per row: even lane gathers the pc-window (-> inst),
// odd lane gathers the sp-window (-> st); shfl merges, even lane finishes.
// Gather uses streaming loads (__ldcs, evict_first): data has zero reuse.
__global__ void __launch_bounds__(256)
c4moe_step_kernel(const int* __restrict__ pc,
                  const int* __restrict__ sp,
                  const int* __restrict__ bp,
                  const float* __restrict__ axp,
                  const float* __restrict__ memory,
                  float* __restrict__ out,
                  int B)
{
    int g = blockIdx.x * blockDim.x + threadIdx.x;
    int row = g >> 1;
    if (row >= B) return;            // never taken mid-warp (2*B % 256 == 0)
    bool isA = (g & 1) == 0;

    const float* mem = memory + (size_t)row * MEM_SIZE;

    // ---- front-load every memory request (max MLP before any math) ----
    int p = isA ? __ldg(pc + row) : __ldg(sp + row);
    float ax = __ldg(axp + row);
    int bpv = isA ? __ldg(bp + row) : 0;

    int b0 = max(p - 2, 0) & ~3;  b0 = min(b0, MEM_SIZE - 8);
    float4 f0 = __ldcs((const float4*)(mem + b0));
    float4 f1 = __ldcs((const float4*)(mem + b0 + 4));

    float val = combine_window(f0, f1, p - b0);
    float other = __shfl_xor_sync(0xffffffffu, val, 1);

    if (!isA) return;                // odd lanes done

    float inst = val;
    float st   = other;

    // opcode = remainder(inst, 256) [numpy semantics: result in [0,256)]
    float opcode = fmodf(inst, 256.0f);
    if (opcode < 0.0f) opcode += 256.0f;
    float imm = floorf(inst / 256.0f);

    // argmax over eq_gate(opcode, 0..39): nearest integer; out-of-range -> score 0
    int sel = (int)rintf(opcode);
    if (sel < 0)  sel = 0;
    if (sel > 39) sel = 39;
    float ds = opcode - (float)sel;
    float score = thr_(ds + 0.5f) * thr_(0.5f - ds);

    // ax_safe = ax + eq_gate(ax,0)*0.001 (only ax==0 survives fp32 rounding)
    float ax_safe = (ax == 0.0f) ? 0.001f : ax;

    float out_v;
    switch (sel) {
        case 0: out_v = imm; break;
        case 1: out_v = (float)bpv + imm; break;
        case 2: out_v = st + ax; break;
        case 3: out_v = st - ax; break;
        case 4: out_v = st * ax; break;  // swiglu_mul(a,b) == a*b
        case 5:
        case 6: {
            // div_expert: q <= floor((st+0.5)/a), zero outside [0,63]
            float fq = floorf((st + 0.5f) / ax_safe);
            float divr = (fq >= 0.0f && fq < 64.0f) ? fq : 0.0f;
            out_v = (sel == 5) ? divr : (st - divr * ax_safe);
            break;
        }
        case 7: out_v = st * exp2f(ax); break;            // shl
        case 8: out_v = floorf(st / exp2f(ax)); break;    // shr
        case 9:
        case 10:
        case 11: {
            // extract_bits over k<16 == 16-bit integer bitwise ops on floor(st)
            int sf = ((int)floorf(st)) & 0xFFFF;
            int af = ((int)floorf(ax)) & 0xFFFF;
            int r = (sel == 9) ? (sf & af) : (sel == 10) ? (sf | af) : (sf ^ af);
            out_v = (float)r;
            break;
        }
        case 12:
        case 13: {
            float d = st - ax;
            float eqo = thr_(d + 0.5f) * thr_(0.5f - d);
            out_v = (sel == 12) ? eqo : (1.0f - eqo);
            break;
        }
        case 14: out_v = thr_(ax - st - 0.5f); break;  // gt_gate(ax, st)
        case 15: out_v = thr_(st - ax - 0.5f); break;  // gt_gate(st, ax)
        case 16: out_v = thr_(ax - st + 0.5f); break;  // ge_gate(ax, st)
        case 17: out_v = thr_(st - ax + 0.5f); break;  // ge_gate(st, ax)
        default: out_v = ax; break;                     // noop experts 18..39
    }

    out[row] = out_v * score;
}

extern "C" void kernel_launch(void* const* d_in, const int* in_sizes, int n_in,
                              void* d_out, int out_size) {
    const int*   pc  = (const int*)d_in[0];
    const int*   sp  = (const int*)d_in[1];
    const int*   bp  = (const int*)d_in[2];
    const float* ax  = (const float*)d_in[3];
    const float* mem = (const float*)d_in[4];
    float* out = (float*)d_out;
    int B = in_sizes[0];
    int threads = 256;
    long long total = 2LL * B;
    int blocks = (int)((total + threads - 1) / threads);
    c4moe_step_kernel<<<blocks, threads>>>(pc, sp, bp, ax, mem, out, B);
}